// round 4
// baseline (speedup 1.0000x reference)
#include <cuda_runtime.h>
#include <cuda_bf16.h>

// Problem constants (from reference)
#define BATCH 1024
#define DDIM  512
#define FDIM  4096

// out[b*D+d] = bias[d] + mask[b*D+d], vectorized float4, grid-stride.
__global__ __launch_bounds__(256)
void tied_init_kernel(float4* __restrict__ out4,
                      const float4* __restrict__ bias4,
                      const float4* __restrict__ mask4,
                      int total4) {
    for (int i = blockIdx.x * blockDim.x + threadIdx.x; i < total4;
         i += gridDim.x * blockDim.x) {
        float4 m = mask4[i];
        float4 bv = bias4[i & (DDIM / 4 - 1)];   // D/4 = 128, power of 2
        m.x += bv.x; m.y += bv.y; m.z += bv.z; m.w += bv.w;
        out4[i] = m;
    }
}

// Weight table (16KB) staged in shared memory: gathers become LDS (smem
// crossbar, ~3-4 cyc avg conflict degree) instead of L1tex gathers that
// touch ~28 lines/warp-instruction. 8 nnz per thread per iteration with
// front-batched LDG.128s; scatter via fire-and-forget atomicAdd (REDG).
__global__ __launch_bounds__(256)
void tied_scatter_kernel(const float4* __restrict__ vals4,
                         const int4* __restrict__ b4,
                         const int4* __restrict__ d4,
                         const int4* __restrict__ f4,
                         const float* __restrict__ w,
                         float* __restrict__ out,
                         int n4) {
    __shared__ float sw[FDIM];

    // Coalesced stage: 4096 floats / 256 threads = 4 float4 per thread.
    {
        const float4* w4 = (const float4*)w;
        float4* sw4 = (float4*)sw;
        #pragma unroll
        for (int k = 0; k < FDIM / 4 / 256; k++) {
            int idx = k * 256 + threadIdx.x;
            sw4[idx] = w4[idx];
        }
    }
    __syncthreads();

    const int S = gridDim.x * blockDim.x;
    int i = blockIdx.x * blockDim.x + threadIdx.x;

    for (; i < n4; i += 2 * S) {
        const int j = i + S;
        const bool has_j = (j < n4);

        // ---- front-batched loads (up to 8x LDG.128) ----
        float4 v0 = vals4[i];
        int4  bi0 = b4[i];
        int4  di0 = d4[i];
        int4  fi0 = f4[i];

        float4 v1;
        int4  bi1, di1, fi1;
        if (has_j) {
            v1  = vals4[j];
            bi1 = b4[j];
            di1 = d4[j];
            fi1 = f4[j];
        }

        // ---- weight gathers from smem ----
        float w00 = sw[fi0.x];
        float w01 = sw[fi0.y];
        float w02 = sw[fi0.z];
        float w03 = sw[fi0.w];

        atomicAdd(&out[bi0.x * DDIM + di0.x], v0.x * w00);
        atomicAdd(&out[bi0.y * DDIM + di0.y], v0.y * w01);
        atomicAdd(&out[bi0.z * DDIM + di0.z], v0.z * w02);
        atomicAdd(&out[bi0.w * DDIM + di0.w], v0.w * w03);

        if (has_j) {
            float w10 = sw[fi1.x];
            float w11 = sw[fi1.y];
            float w12 = sw[fi1.z];
            float w13 = sw[fi1.w];

            atomicAdd(&out[bi1.x * DDIM + di1.x], v1.x * w10);
            atomicAdd(&out[bi1.y * DDIM + di1.y], v1.y * w11);
            atomicAdd(&out[bi1.z * DDIM + di1.z], v1.z * w12);
            atomicAdd(&out[bi1.w * DDIM + di1.w], v1.w * w13);
        }
    }
}

// Tail handler for NNZ not divisible by 4 (defensive; NNZ=10M is divisible).
__global__ __launch_bounds__(256)
void tied_scatter_tail_kernel(const float* __restrict__ vals,
                              const int* __restrict__ b,
                              const int* __restrict__ d,
                              const int* __restrict__ f,
                              const float* __restrict__ w,
                              float* __restrict__ out,
                              int start, int n) {
    int i = start + blockIdx.x * blockDim.x + threadIdx.x;
    if (i >= n) return;
    atomicAdd(&out[b[i] * DDIM + d[i]], vals[i] * __ldg(&w[f[i]]));
}

extern "C" void kernel_launch(void* const* d_in, const int* in_sizes, int n_in,
                              void* d_out, int out_size) {
    // metadata order: values, b_idx, d_idx, f_idx, weight, bias, mask
    const float* values = (const float*)d_in[0];
    const int*   b_idx  = (const int*)d_in[1];
    const int*   d_idx  = (const int*)d_in[2];
    const int*   f_idx  = (const int*)d_in[3];
    const float* weight = (const float*)d_in[4];
    const float* bias   = (const float*)d_in[5];
    const float* mask   = (const float*)d_in[6];
    float* out = (float*)d_out;

    const int nnz = in_sizes[0];
    const int THREADS = 256;
    const int MAX_BLOCKS = 148 * 8;

    // 1) init: out = bias + mask  (out_size = B*D = 524288, /4 = 131072)
    {
        int total4 = out_size / 4;
        int blocks = (total4 + THREADS - 1) / THREADS;
        if (blocks > MAX_BLOCKS) blocks = MAX_BLOCKS;
        tied_init_kernel<<<blocks, THREADS>>>((float4*)out,
                                              (const float4*)bias,
                                              (const float4*)mask,
                                              total4);
    }

    // 2) scatter
    {
        int n4 = nnz / 4;
        int blocks = (n4 + THREADS - 1) / THREADS;
        if (blocks > MAX_BLOCKS) blocks = MAX_BLOCKS;
        tied_scatter_kernel<<<blocks, THREADS>>>((const float4*)values,
                                                 (const int4*)b_idx,
                                                 (const int4*)d_idx,
                                                 (const int4*)f_idx,
                                                 weight, out, n4);
        int tail_start = n4 * 4;
        int tail = nnz - tail_start;
        if (tail > 0) {
            tied_scatter_tail_kernel<<<1, 256>>>(values, b_idx, d_idx, f_idx,
                                                 weight, out, tail_start, nnz);
        }
    }
}

// round 6
// speedup vs baseline: 1.0289x; 1.0289x over previous
#include <cuda_runtime.h>
#include <cuda_bf16.h>

// Problem constants (from reference)
#define BATCH 1024
#define DDIM  512
#define FDIM  4096

// out[b*D+d] = bias[d] + mask[b*D+d], vectorized float4, grid-stride.
__global__ __launch_bounds__(256)
void tied_init_kernel(float4* __restrict__ out4,
                      const float4* __restrict__ bias4,
                      const float4* __restrict__ mask4,
                      int total4) {
    for (int i = blockIdx.x * blockDim.x + threadIdx.x; i < total4;
         i += gridDim.x * blockDim.x) {
        float4 m = mask4[i];
        float4 bv = bias4[i & (DDIM / 4 - 1)];   // D/4 = 128, power of 2
        m.x += bv.x; m.y += bv.y; m.z += bv.z; m.w += bv.w;
        out4[i] = m;
    }
}

// One-shot kernel: each thread handles exactly 8 nnz (two float4/int4 chunks,
// all 8 LDG.128s issued up front). No persistent loop -> ~4 waves of medium
// blocks -> hardware wave scheduling absorbs per-SM finish-time spread.
// Scatter via fire-and-forget atomicAdd (REDG) into the L2-resident output.
__global__ __launch_bounds__(256)
void tied_scatter_kernel(const float4* __restrict__ vals4,
                         const int4* __restrict__ b4,
                         const int4* __restrict__ d4,
                         const int4* __restrict__ f4,
                         const float* __restrict__ w,
                         float* __restrict__ out,
                         int n4) {
    const int base = blockIdx.x * (2 * 256) + threadIdx.x;
    const int i = base;            // chunk 0
    const int j = base + 256;      // chunk 1 (same block, +256: coalesced)

    // Fast path: whole block in range (true for all but the last block).
    if (blockIdx.x * (2 * 256) + 2 * 256 <= n4) {
        float4 v0 = vals4[i];
        int4  bi0 = b4[i];
        int4  di0 = d4[i];
        int4  fi0 = f4[i];
        float4 v1 = vals4[j];
        int4  bi1 = b4[j];
        int4  di1 = d4[j];
        int4  fi1 = f4[j];

        float w00 = __ldg(&w[fi0.x]);
        float w01 = __ldg(&w[fi0.y]);
        float w02 = __ldg(&w[fi0.z]);
        float w03 = __ldg(&w[fi0.w]);
        float w10 = __ldg(&w[fi1.x]);
        float w11 = __ldg(&w[fi1.y]);
        float w12 = __ldg(&w[fi1.z]);
        float w13 = __ldg(&w[fi1.w]);

        atomicAdd(&out[bi0.x * DDIM + di0.x], v0.x * w00);
        atomicAdd(&out[bi0.y * DDIM + di0.y], v0.y * w01);
        atomicAdd(&out[bi0.z * DDIM + di0.z], v0.z * w02);
        atomicAdd(&out[bi0.w * DDIM + di0.w], v0.w * w03);
        atomicAdd(&out[bi1.x * DDIM + di1.x], v1.x * w10);
        atomicAdd(&out[bi1.y * DDIM + di1.y], v1.y * w11);
        atomicAdd(&out[bi1.z * DDIM + di1.z], v1.z * w12);
        atomicAdd(&out[bi1.w * DDIM + di1.w], v1.w * w13);
        return;
    }

    // Slow path: last (partial) block only.
    if (i < n4) {
        float4 v0 = vals4[i];
        int4  bi0 = b4[i];
        int4  di0 = d4[i];
        int4  fi0 = f4[i];
        atomicAdd(&out[bi0.x * DDIM + di0.x], v0.x * __ldg(&w[fi0.x]));
        atomicAdd(&out[bi0.y * DDIM + di0.y], v0.y * __ldg(&w[fi0.y]));
        atomicAdd(&out[bi0.z * DDIM + di0.z], v0.z * __ldg(&w[fi0.z]));
        atomicAdd(&out[bi0.w * DDIM + di0.w], v0.w * __ldg(&w[fi0.w]));
    }
    if (j < n4) {
        float4 v1 = vals4[j];
        int4  bi1 = b4[j];
        int4  di1 = d4[j];
        int4  fi1 = f4[j];
        atomicAdd(&out[bi1.x * DDIM + di1.x], v1.x * __ldg(&w[fi1.x]));
        atomicAdd(&out[bi1.y * DDIM + di1.y], v1.y * __ldg(&w[fi1.y]));
        atomicAdd(&out[bi1.z * DDIM + di1.z], v1.z * __ldg(&w[fi1.z]));
        atomicAdd(&out[bi1.w * DDIM + di1.w], v1.w * __ldg(&w[fi1.w]));
    }
}

// Tail handler for NNZ not divisible by 4 (defensive; NNZ=10M is divisible).
__global__ __launch_bounds__(256)
void tied_scatter_tail_kernel(const float* __restrict__ vals,
                              const int* __restrict__ b,
                              const int* __restrict__ d,
                              const int* __restrict__ f,
                              const float* __restrict__ w,
                              float* __restrict__ out,
                              int start, int n) {
    int i = start + blockIdx.x * blockDim.x + threadIdx.x;
    if (i >= n) return;
    atomicAdd(&out[b[i] * DDIM + d[i]], vals[i] * __ldg(&w[f[i]]));
}

extern "C" void kernel_launch(void* const* d_in, const int* in_sizes, int n_in,
                              void* d_out, int out_size) {
    // metadata order: values, b_idx, d_idx, f_idx, weight, bias, mask
    const float* values = (const float*)d_in[0];
    const int*   b_idx  = (const int*)d_in[1];
    const int*   d_idx  = (const int*)d_in[2];
    const int*   f_idx  = (const int*)d_in[3];
    const float* weight = (const float*)d_in[4];
    const float* bias   = (const float*)d_in[5];
    const float* mask   = (const float*)d_in[6];
    float* out = (float*)d_out;

    const int nnz = in_sizes[0];
    const int THREADS = 256;

    // 1) init: out = bias + mask  (out_size = B*D = 524288, /4 = 131072)
    {
        int total4 = out_size / 4;
        int blocks = (total4 + THREADS - 1) / THREADS;
        int maxb = 148 * 8;
        if (blocks > maxb) blocks = maxb;
        tied_init_kernel<<<blocks, THREADS>>>((float4*)out,
                                              (const float4*)bias,
                                              (const float4*)mask,
                                              total4);
    }

    // 2) scatter: each block consumes 512 4-nnz packets (2048 nnz)
    {
        int n4 = nnz / 4;
        int per_block = 2 * THREADS;               // 512 packets
        int blocks = (n4 + per_block - 1) / per_block;
        tied_scatter_kernel<<<blocks, THREADS>>>((const float4*)values,
                                                 (const int4*)b_idx,
                                                 (const int4*)d_idx,
                                                 (const int4*)f_idx,
                                                 weight, out, n4);
        int tail_start = n4 * 4;
        int tail = nnz - tail_start;
        if (tail > 0) {
            tied_scatter_tail_kernel<<<1, 256>>>(values, b_idx, d_idx, f_idx,
                                                 weight, out, tail_start, nnz);
        }
    }
}